// round 15
// baseline (speedup 1.0000x reference)
#include <cuda_runtime.h>
#include <cuda_bf16.h>
#include <stdint.h>
#include <math.h>

#define BB 512
#define DD 128
#define NLAT 16
#define NH 4
#define HDIM 32
#define ND 25600
#define NE 153600
#define NPAIR 64
#define LAYERS 4

// scratch (static device globals: allowed)
__device__ float g_lat[BB * NLAT * DD];
__device__ uint32_t g_ctxAP[BB * 16384];   // ctx in A-frag packed order: [b][ks0..63][lane][word]
__device__ int   g_starts[2][BB + 1];
__device__ __nv_bfloat16 g_dk[ND * DD];
__device__ __nv_bfloat16 g_dv[ND * DD];
__device__ __nv_bfloat16 g_ek[NE * DD];
__device__ __nv_bfloat16 g_ev[NE * DD];
// composed weights, MMA B-fragment packed: [n_tile][kstep][lane][2 words]
__device__ uint32_t g_AqP[LAYERS * 2 * 32768];
__device__ float g_cq[LAYERS * 2 * 512];
__device__ uint32_t g_BvoP[LAYERS * 65536];
__device__ float g_cvo[LAYERS * 2 * 128];
__device__ uint32_t g_w1P[LAYERS * 16384];
__device__ uint32_t g_w2P[LAYERS * 16384];
// precompute scratch
__device__ float g_P[32 * 32 * 128];
__device__ float g_cb[32 * 32];

__device__ __forceinline__ int lb_dev(const int* __restrict__ a, int n, int key) {
    int lo = 0, hi = n;
    while (lo < hi) { int mid = (lo + hi) >> 1; if (a[mid] < key) lo = mid + 1; else hi = mid; }
    return lo;
}

__device__ __forceinline__ uint32_t f2bf2(float x, float y) {
    __nv_bfloat162 h = __floats2bfloat162_rn(x, y);
    return *reinterpret_cast<uint32_t*>(&h);
}

// frag scatter: element (n, k pair j) -> lane = (n&7)*4 + (j&3), word = j>>2
__device__ __forceinline__ void frag_store8(uint32_t* base32, int n_in, const float* acc, float scl) {
    #pragma unroll
    for (int j = 0; j < 8; j++) {
        int lane = n_in * 4 + (j & 3);
        int word = j >> 2;
        base32[lane * 2 + word] = f2bf2(acc[2 * j] * scl, acc[2 * j + 1] * scl);
    }
}

// ---------------- mega setup ----------------
#define PCP0 0
#define PCB0 128
#define CVO0 256
#define FFN0 264
#define OFF0 268
#define INIT0 271
#define CVT0 4367
#define SETUP_GRID 23567

__global__ void __launch_bounds__(256) mega_setup_kernel(
    const float* __restrict__ dk, const float* __restrict__ dv,
    const float* __restrict__ ek, const float* __restrict__ ev,
    const int* __restrict__ db, const int* __restrict__ eb,
    const float* __restrict__ latents,
    const float* __restrict__ wq_d, const float* __restrict__ bq_d,
    const float* __restrict__ wq_e, const float* __restrict__ bq_e,
    const float* __restrict__ mw_d, const float* __restrict__ mb_d,
    const float* __restrict__ ow_d, const float* __restrict__ ob_d,
    const float* __restrict__ mw_e, const float* __restrict__ mb_e,
    const float* __restrict__ ow_e, const float* __restrict__ ob_e,
    const float* __restrict__ w1, const float* __restrict__ w2) {
    __shared__ float sb[8224];
    int bid = blockIdx.x, t = threadIdx.x;

    if (bid >= CVT0) {
        int i = (bid - CVT0) * 256 + t;
        int i4 = i * 4;
        if (i4 < ND * DD) {
            float4 a = *(const float4*)(dk + i4);
            float4 b = *(const float4*)(dv + i4);
            *(uint2*)(g_dk + i4) = make_uint2(f2bf2(a.x, a.y), f2bf2(a.z, a.w));
            *(uint2*)(g_dv + i4) = make_uint2(f2bf2(b.x, b.y), f2bf2(b.z, b.w));
        }
        if (i4 < NE * DD) {
            float4 a = *(const float4*)(ek + i4);
            float4 b = *(const float4*)(ev + i4);
            *(uint2*)(g_ek + i4) = make_uint2(f2bf2(a.x, a.y), f2bf2(a.z, a.w));
            *(uint2*)(g_ev + i4) = make_uint2(f2bf2(b.x, b.y), f2bf2(b.z, b.w));
        }
        return;
    }
    if (bid >= INIT0) {
        int i = (bid - INIT0) * 256 + t;
        if (i < BB * NLAT * DD) g_lat[i] = latents[i & (NLAT * DD - 1)];
        return;
    }
    if (bid >= OFF0) {
        int i = (bid - OFF0) * 256 + t;
        if (i <= BB) { g_starts[0][i] = lb_dev(db, ND, i); g_starts[1][i] = lb_dev(eb, NE, i); }
        return;
    }
    if (bid >= FFN0) {
        int l = bid - FFN0;
        {
            const float* src = w1 + (size_t)l * 2 * DD * DD + (size_t)t * DD;
            int n_t = t >> 3, n_in = t & 7;
            for (int ks = 0; ks < 8; ks++) {
                float v[16];
                #pragma unroll
                for (int q = 0; q < 4; q++) {
                    float4 f = *(const float4*)(src + ks * 16 + q * 4);
                    v[q*4+0] = f.x; v[q*4+1] = f.y; v[q*4+2] = f.z; v[q*4+3] = f.w;
                }
                frag_store8(g_w1P + (size_t)l * 16384 + (size_t)(n_t * 8 + ks) * 64, n_in, v, 1.0f);
            }
        }
        {
            int n = t & 127, half = t >> 7;
            const float* src = w2 + (size_t)l * DD * 2 * DD + (size_t)n * 2 * DD;
            int n_t = n >> 3, n_in = n & 7;
            for (int kk = 0; kk < 8; kk++) {
                int ks = half * 8 + kk;
                float v[16];
                #pragma unroll
                for (int q = 0; q < 4; q++) {
                    float4 f = *(const float4*)(src + ks * 16 + q * 4);
                    v[q*4+0] = f.x; v[q*4+1] = f.y; v[q*4+2] = f.z; v[q*4+3] = f.w;
                }
                frag_store8(g_w2P + (size_t)l * 16384 + (size_t)(n_t * 16 + ks) * 64, n_in, v, 1.0f);
            }
        }
        return;
    }
    if (bid >= CVO0) {
        int r = bid - CVO0;
        int m = r & 1, l = r >> 1;
        const float* ow = (m ? ow_e : ow_d) + (size_t)l * DD * DD;
        const float* ob = (m ? ob_e : ob_d) + l * DD;
        const float* bv = (m ? mb_e : mb_d) + l * 3 * DD + 2 * DD;
        float* bv_s = sb;
        if (t < 128) bv_s[t] = bv[t];
        __syncthreads();
        if (t < 128) {
            float s = ob[t];
            const float4* owr = (const float4*)(ow + (size_t)t * 128);
            #pragma unroll
            for (int u4 = 0; u4 < 32; u4++) {
                float4 o4 = owr[u4];
                s = fmaf(o4.x, bv_s[u4*4+0], fmaf(o4.y, bv_s[u4*4+1],
                    fmaf(o4.z, bv_s[u4*4+2], fmaf(o4.w, bv_s[u4*4+3], s))));
            }
            g_cvo[(l * 2 + m) * 128 + t] = s;
        }
        return;
    }
    if (bid >= PCB0) {
        int r = bid - PCB0;
        int c = r >> 2, ts = r & 3;
        int h = c & 3, m = (c >> 2) & 1, l = c >> 3;
        const float* W  = (m ? mw_e : mw_d) + (size_t)l * 3 * DD * DD;
        const float* ow = (m ? ow_e : ow_d) + (size_t)l * DD * DD;
        float* wv_s = sb;
        float* ow_s = sb + 4096;
        for (int i = t; i < 1024; i += 256)
            ((float4*)wv_s)[i] = ((const float4*)(W + (size_t)(2 * DD + h * 32) * DD))[i];
        for (int i = t; i < 1024; i += 256) {
            int tpl = i >> 5, j = i & 31;
            ow_s[tpl * 32 + j] = ow[(size_t)(ts * 32 + tpl) * 128 + h * 32 + j];
        }
        __syncthreads();
        int tpl = t >> 3, d0 = (t & 7) * 16;
        float acc[16];
        #pragma unroll
        for (int i = 0; i < 16; i++) acc[i] = 0.0f;
        for (int j = 0; j < 32; j++) {
            float o = ow_s[tpl * 32 + j];
            const float4* wr = (const float4*)(wv_s + j * 128 + d0);
            #pragma unroll
            for (int q = 0; q < 4; q++) {
                float4 w4 = wr[q];
                acc[q*4+0] = fmaf(o, w4.x, acc[q*4+0]);
                acc[q*4+1] = fmaf(o, w4.y, acc[q*4+1]);
                acc[q*4+2] = fmaf(o, w4.z, acc[q*4+2]);
                acc[q*4+3] = fmaf(o, w4.w, acc[q*4+3]);
            }
        }
        int n = ts * 32 + tpl;
        int kk0 = m * 512 + h * 128 + d0;
        int n_t = n >> 3, n_in = n & 7, ks = kk0 >> 4;
        frag_store8(g_BvoP + (size_t)l * 65536 + (size_t)(n_t * 64 + ks) * 64, n_in, acc, 1.0f);
        return;
    }
    {
        int r = bid - PCP0;
        int c = r >> 2, ds = r & 3;
        int h = c & 3, m = (c >> 2) & 1, l = c >> 3;
        const float* wq = (m ? wq_e : wq_d) + (size_t)l * DD * DD;
        const float* W  = (m ? mw_e : mw_d) + (size_t)l * 3 * DD * DD;
        float* U_s = sb;
        float* wq_s = sb + 4096;
        for (int i = t; i < 1024; i += 256)
            ((float4*)U_s)[i] = ((const float4*)(W + (size_t)h * 32 * DD))[i];
        for (int i = t; i < 1024; i += 256) {
            int dp = i >> 3, q = i & 7;
            *(float4*)(wq_s + dp * 32 + q * 4) = *(const float4*)(wq + (size_t)dp * 128 + ds * 32 + q * 4);
        }
        __syncthreads();
        int j = t >> 3, dl = (t & 7) * 4;
        float a0 = 0, a1 = 0, a2 = 0, a3 = 0;
        #pragma unroll 8
        for (int dp = 0; dp < 128; dp++) {
            float u = U_s[j * 128 + dp];
            float4 w4 = *(const float4*)(wq_s + dp * 32 + dl);
            a0 = fmaf(u, w4.x, a0); a1 = fmaf(u, w4.y, a1);
            a2 = fmaf(u, w4.z, a2); a3 = fmaf(u, w4.w, a3);
        }
        *(float4*)(g_P + (size_t)c * 4096 + j * 128 + ds * 32 + dl) = make_float4(a0, a1, a2, a3);
        if (ds == 0 && t < 32) {
            const float* bq = (m ? bq_e : bq_d) + l * DD;
            const float* mb = (m ? mb_e : mb_d) + l * 3 * DD;
            float s = 0.0f;
            #pragma unroll 8
            for (int dp = 0; dp < 128; dp++) s += U_s[t * 128 + dp] * bq[dp];
            g_cb[c * 32 + t] = s + mb[h * 32 + t];
        }
    }
}

// pc_Aq depends on g_P -> separate launch
__global__ void __launch_bounds__(256) pc_Aq_kernel(
    const float* __restrict__ mw_d, const float* __restrict__ mw_e) {
    __shared__ float P_s[32 * 128];
    __shared__ float V_s[32 * 32];
    __shared__ float cb_s[32];
    int c = blockIdx.x, ts = blockIdx.y, t = threadIdx.x;
    int h = c & 3, m = (c >> 2) & 1, l = c >> 3;
    const float* W = (m ? mw_e : mw_d) + (size_t)l * 3 * DD * DD;
    const float* wk = W + (size_t)(DD + h * 32) * DD;
    for (int i = t; i < 1024; i += 256)
        ((float4*)P_s)[i] = ((const float4*)(g_P + (size_t)c * 4096))[i];
    for (int i = t; i < 1024; i += 256) {
        int j = i >> 5, tpl = i & 31;
        V_s[j * 32 + tpl] = wk[(size_t)j * 128 + ts * 32 + tpl];
    }
    if (t < 32) cb_s[t] = g_cb[c * 32 + t];
    __syncthreads();
    const float scale = 0.17677669529663688f;
    int tpl = t >> 3, d0 = (t & 7) * 16;
    float acc[16];
    #pragma unroll
    for (int i = 0; i < 16; i++) acc[i] = 0.0f;
    float cq = 0.0f;
    for (int j = 0; j < 32; j++) {
        float v = V_s[j * 32 + tpl];
        const float4* pr = (const float4*)(P_s + j * 128 + d0);
        #pragma unroll
        for (int q = 0; q < 4; q++) {
            float4 p4 = pr[q];
            acc[q*4+0] = fmaf(v, p4.x, acc[q*4+0]);
            acc[q*4+1] = fmaf(v, p4.y, acc[q*4+1]);
            acc[q*4+2] = fmaf(v, p4.z, acc[q*4+2]);
            acc[q*4+3] = fmaf(v, p4.w, acc[q*4+3]);
        }
        cq += v * cb_s[j];
    }
    int n = ts * 32 + tpl;
    int n_t = n >> 3, n_in = n & 7, ks = t & 7;
    frag_store8(g_AqP + (size_t)(l * 2 + m) * 32768 + (size_t)(n_t * 8 + ks) * 64, n_in, acc, scale);
    if ((t & 7) == 0) g_cq[(l * 2 + m) * 512 + n] = cq * scale;
}

// ---------------- common helpers ----------------
__device__ __forceinline__ void layernorm_rows(const float* __restrict__ src,
                                               const float* __restrict__ g,
                                               const float* __restrict__ bta,
                                               float (*dst)[DD], int t, int nthr) {
    int warp = t >> 5, lane = t & 31, nw = nthr >> 5;
    for (int r = warp; r < NLAT; r += nw) {
        float4 v = ((const float4*)(src + r * DD))[lane];
        float s = v.x + v.y + v.z + v.w;
        #pragma unroll
        for (int o = 16; o; o >>= 1) s += __shfl_xor_sync(0xffffffffu, s, o);
        float mean = s * (1.0f / DD);
        float dx = v.x - mean, dy = v.y - mean, dz = v.z - mean, dw = v.w - mean;
        float q = dx * dx + dy * dy + dz * dz + dw * dw;
        #pragma unroll
        for (int o = 16; o; o >>= 1) q += __shfl_xor_sync(0xffffffffu, q, o);
        float rstd = rsqrtf(q * (1.0f / DD) + 1e-5f);
        int c = lane * 4;
        dst[r][c + 0] = dx * rstd * g[c + 0] + bta[c + 0];
        dst[r][c + 1] = dy * rstd * g[c + 1] + bta[c + 1];
        dst[r][c + 2] = dz * rstd * g[c + 2] + bta[c + 2];
        dst[r][c + 3] = dw * rstd * g[c + 3] + bta[c + 3];
    }
}

__device__ __forceinline__ uint32_t s2u(const void* p) {
    return (uint32_t)__cvta_generic_to_shared(p);
}

#define LDSM4(R, addr) asm volatile( \
    "ldmatrix.sync.aligned.m8n8.x4.shared.b16 {%0,%1,%2,%3},[%4];" \
    : "=r"((R)[0]), "=r"((R)[1]), "=r"((R)[2]), "=r"((R)[3]) : "r"(addr))
#define LDSM4T(R, addr) asm volatile( \
    "ldmatrix.sync.aligned.m8n8.x4.trans.shared.b16 {%0,%1,%2,%3},[%4];" \
    : "=r"((R)[0]), "=r"((R)[1]), "=r"((R)[2]), "=r"((R)[3]) : "r"(addr))
#define MMA16816(D, A, B0, B1) asm volatile( \
    "mma.sync.aligned.m16n8k16.row.col.f32.bf16.bf16.f32 " \
    "{%0,%1,%2,%3},{%4,%5,%6,%7},{%8,%9},{%0,%1,%2,%3};" \
    : "+f"((D)[0]), "+f"((D)[1]), "+f"((D)[2]), "+f"((D)[3]) \
    : "r"((A)[0]), "r"((A)[1]), "r"((A)[2]), "r"((A)[3]), "r"(B0), "r"(B1))
#define CP16(dst, src) asm volatile("cp.async.cg.shared.global [%0], [%1], 16;\n" :: "r"(dst), "l"(src))
#define CP_COMMIT() asm volatile("cp.async.commit_group;\n" ::: "memory")
#define CP_WAIT1() asm volatile("cp.async.wait_group 1;\n" ::: "memory")
#define CP_WAIT0() asm volatile("cp.async.wait_group 0;\n" ::: "memory")

// ---------------- fused attention: LN + Q-GEMM prologue + flash attention ----------------
#define KV_ELE (64 * 136)
#define ATT_BYTES (4 * KV_ELE * 2 + 64 * 72 * 2 + 64 * 68 * 4 + 3 * 64 * 4)

__device__ __forceinline__ void issue_chunk(const __nv_bfloat16* __restrict__ Kg,
                                            const __nv_bfloat16* __restrict__ Vg,
                                            __nv_bfloat16* Ksb, __nv_bfloat16* Vsb,
                                            int row0, int nk, int t) {
    #pragma unroll
    for (int i = t; i < 1024; i += 256) {
        int r = i >> 4, seg = (i & 15) * 8;
        if (r < nk) {
            CP16(s2u(Ksb + r * 136 + seg), Kg + (size_t)(row0 + r) * DD + seg);
            CP16(s2u(Vsb + r * 136 + seg), Vg + (size_t)(row0 + r) * DD + seg);
        }
    }
}

// grid 1024: bid<512 -> enzyme first, else drug. 256 threads.
__global__ void __launch_bounds__(256, 2) attn_kernel(int layer,
    const float* __restrict__ lng, const float* __restrict__ lnb) {
    extern __shared__ char smraw[];
    __nv_bfloat16* Ks0 = (__nv_bfloat16*)smraw;
    __nv_bfloat16* Vs0 = Ks0 + 2 * KV_ELE;
    __nv_bfloat16* Ps  = Vs0 + 2 * KV_ELE;
    float* ss  = (float*)(Ps + 64 * 72);
    float* m_s = ss + 64 * 68;
    float* l_s = m_s + 64;
    float* sc_s = l_s + 64;
    float* nlf = (float*)Ps;
    __nv_bfloat16* nlh = Vs0 + KV_ELE;
    __nv_bfloat16* qts = (__nv_bfloat16*)ss;

    int bid = blockIdx.x, t = threadIdx.x;
    int mod = (bid < 512) ? 1 : 0;
    int b = bid & 511;
    const __nv_bfloat16* Kg = mod ? g_ek : g_dk;
    const __nv_bfloat16* Vg = mod ? g_ev : g_dv;
    int w = t >> 5, lane = t & 31;
    int g = lane >> 2, tc = lane & 3;
    int s0 = g_starts[mod][b];
    int cnt = g_starts[mod][b + 1] - s0;

    int pb = (w & 3) * 16;
    int th = w >> 2;

    for (int i = t; i < (4 * KV_ELE * 2) / 16; i += 256)
        ((uint4*)smraw)[i] = make_uint4(0, 0, 0, 0);
    __syncthreads();

    int nchunks = (cnt + 63) >> 6;
    if (nchunks > 0) {
        issue_chunk(Kg, Vg, Ks0, Vs0, s0, min(64, cnt), t);
        CP_COMMIT();
    }

    layernorm_rows(g_lat + (size_t)b * NLAT * DD, lng, lnb, (float(*)[DD])nlf, t, 256);
    __syncthreads();
    for (int i = t; i < NLAT * DD / 2; i += 256) {
        int r = i >> 6, c = (i & 63) * 2;
        *(uint32_t*)(nlh + r * 136 + c) = f2bf2(nlf[r * DD + c], nlf[r * DD + c + 1]);
    }
    __syncthreads();
    {
        const uint32_t* AqP = g_AqP + (size_t)(layer * 2 + mod) * 32768;
        const float* cq = g_cq + (layer * 2 + mod) * 512;
        uint32_t aN = s2u(nlh + (lane & 15) * 136 + (lane >> 4) * 8);
        float acc[8][4];
        #pragma unroll
        for (int i = 0; i < 8; i++)
            #pragma unroll
            for (int j = 0; j < 4; j++) acc[i][j] = 0.0f;
        #pragma unroll
        for (int ks = 0; ks < 8; ks++) {
            uint32_t aA[4];
            LDSM4(aA, aN + ks * 32);
            #pragma unroll
            for (int nt = 0; nt < 8; nt++) {
                int n_t = w * 8 + nt;
                uint2 bb = *(const uint2*)(AqP + (size_t)(n_t * 8 + ks) * 64 + lane * 2);
                MMA16816(acc[nt], aA, bb.x, bb.y);
            }
        }
        #pragma unroll
        for (int nt = 0; nt < 8; nt++) {
            int n0 = w * 64 + nt * 8 + tc * 2;
            int h = n0 >> 7, col = n0 & 127;
            float c0v = cq[n0], c1v = cq[n0 + 1];
            *(uint32_t*)(qts + (g * 4 + h) * 136 + col)       = f2bf2(acc[nt][0] + c0v, acc[nt][1] + c1v);
            *(uint32_t*)(qts + ((g + 8) * 4 + h) * 136 + col) = f2bf2(acc[nt][2] + c0v, acc[nt][3] + c1v);
        }
    }
    __syncthreads();
    uint32_t qa[8][4];
    {
        uint32_t aQ = s2u(qts + (pb + (lane & 15)) * 136 + (lane >> 4) * 8);
        #pragma unroll
        for (int ks = 0; ks < 8; ks++) LDSM4(qa[ks], aQ + ks * 32);
    }
    if (t < 64) { m_s[t] = -1e30f; l_s[t] = 0.0f; }

    float cx[8][4];
    #pragma unroll
    for (int i = 0; i < 8; i++)
        #pragma unroll
        for (int j = 0; j < 4; j++) cx[i][j] = 0.0f;

    uint32_t aK1 = s2u(Ks0 + (th * 32 + ((lane >> 4) << 3) + (lane & 7)) * 136 + ((lane >> 3) & 1) * 8);
    uint32_t aK2 = aK1 + 16 * 136 * 2;
    uint32_t aP  = s2u(Ps + (pb + (lane & 15)) * 72 + (lane >> 4) * 8);
    uint32_t aV  = s2u(Vs0 + (lane & 15) * 136 + th * 64 + (lane >> 4) * 8);

    for (int k = 0; k < nchunks; k++) {
        int cur = k & 1;
        int nk = min(64, cnt - k * 64);
        if (k + 1 < nchunks) {
            int nk2 = min(64, cnt - (k + 1) * 64);
            issue_chunk(Kg, Vg, Ks0 + (cur ^ 1) * KV_ELE, Vs0 + (cur ^ 1) * KV_ELE,
                        s0 + (k + 1) * 64, nk2, t);
            CP_COMMIT();
            CP_WAIT1();
        } else {
            CP_WAIT0();
        }
        __syncthreads();
        {
            uint32_t kbase1 = aK1 + cur * (KV_ELE * 2);
            uint32_t kbase2 = aK2 + cur * (KV_ELE * 2);
            float sa[4][4];
            #pragma unroll
            for (int j = 0; j < 4; j++)
                #pragma unroll
                for (int q = 0; q < 4; q++) sa[j][q] = 0.0f;
            #pragma unroll
            for (int ks = 0; ks < 8; ks++) {
                uint32_t kb1[4], kb2[4];
                LDSM4(kb1, kbase1 + ks * 32);
                LDSM4(kb2, kbase2 + ks * 32);
                MMA16816(sa[0], qa[ks], kb1[0], kb1[1]);
                MMA16816(sa[1], qa[ks], kb1[2], kb1[3]);
                MMA16816(sa[2], qa[ks], kb2[0], kb2[1]);
                MMA16816(sa[3], qa[ks], kb2[2], kb2[3]);
            }
            int r0 = pb + g, r1 = pb + g + 8;
            #pragma unroll
            for (int j = 0; j < 4; j++) {
                int c0 = th * 32 + j * 8 + tc * 2;
                *(float2*)&ss[r0 * 68 + c0] = make_float2(sa[j][0], sa[j][1]);
                *(float2*)&ss[r1 * 68 + c0] = make_float2(sa[j][2], sa[j][3]);
            }
        }
        __syncthreads();
        {
            int p = t >> 2, sub = t & 3;
            int k0 = sub * 16;
            float mo = m_s[p];
            float cm = -1e30f;
            #pragma unroll 4
            for (int kk = k0; kk < k0 + 16; kk++) {
                float v = (kk < nk) ? ss[p * 68 + kk] : -1e30f;
                cm = fmaxf(cm, v);
            }
            cm = fmaxf(cm, __shfl_xor_sync(0xffffffffu, cm, 1));
            cm = fmaxf(cm, __shfl_xor_sync(0xffffffffu, cm, 2));
            cm = fmaxf(cm, mo);
            float sum = 0.0f;
            #pragma unroll 4
            for (int kk = k0; kk < k0 + 16; kk++) {
                float e = (kk < nk) ? __expf(ss[p * 68 + kk] - cm) : 0.0f;
                Ps[p * 72 + kk] = __float2bfloat16(e);
                sum += e;
            }
            sum += __shfl_xor_sync(0xffffffffu, sum, 1);
            sum += __shfl_xor_sync(0xffffffffu, sum, 2);
            if (sub == 0) {
                float scl = __expf(mo - cm);
                l_s[p] = l_s[p] * scl + sum;
                m_s[p] = cm;
                sc_s[p] = scl;
            }
        }
        __syncthreads();
        {
            uint32_t vbase = aV + cur * (KV_ELE * 2);
            float sc0 = sc_s[pb + g], sc1 = sc_s[pb + g + 8];
            #pragma unroll
            for (int nt = 0; nt < 8; nt++) {
                cx[nt][0] *= sc0; cx[nt][1] *= sc0;
                cx[nt][2] *= sc1; cx[nt][3] *= sc1;
            }
            #pragma unroll
            for (int ks = 0; ks < 4; ks++) {
                uint32_t pa[4];
                LDSM4(pa, aP + ks * 32);
                #pragma unroll
                for (int ntp = 0; ntp < 4; ntp++) {
                    uint32_t vb[4];
                    LDSM4T(vb, vbase + ks * 4352 + ntp * 32);
                    MMA16816(cx[ntp * 2 + 0], pa, vb[0], vb[1]);
                    MMA16816(cx[ntp * 2 + 1], pa, vb[2], vb[3]);
                }
            }
        }
        __syncthreads();
    }
    // epilogue: normalize + store ctx directly in A-fragment-packed global layout
    int r0 = pb + g, r1 = pb + g + 8;
    float l0 = l_s[r0], l1 = l_s[r1];
    float inv0 = (l0 > 0.0f) ? 1.0f / l0 : 0.0f;
    float inv1 = (l1 > 0.0f) ? 1.0f / l1 : 0.0f;
    uint32_t* cap = g_ctxAP + (size_t)b * 16384;
    int li0 = r0 >> 2, li1 = r1 >> 2;
    int ksb = mod * 32 + (r0 & 3) * 8 + th * 4;
    #pragma unroll
    for (int nt = 0; nt < 8; nt++) {
        int ks = ksb + (nt >> 1);
        int wadd = 2 * (nt & 1);
        cap[ks * 128 + ((li0 & 7) * 4 + tc) * 4 + (li0 >> 3) + wadd] = f2bf2(cx[nt][0] * inv0, cx[nt][1] * inv0);
        cap[ks * 128 + ((li1 & 7) * 4 + tc) * 4 + (li1 >> 3) + wadd] = f2bf2(cx[nt][2] * inv1, cx[nt][3] * inv1);
    }
}

// ---------------- fused VO + LN2 + FFN, 2 batches/block, A-frags from global ----------------
__global__ void __launch_bounds__(256) projffn_kernel(int layer,
    const float* __restrict__ lng, const float* __restrict__ lnb,
    const float* __restrict__ b1, const float* __restrict__ b2) {
    __shared__ float latv[2][2048];                       // 16384 B
    __shared__ __nv_bfloat16 nlh[2][2176];                // 8704 B ([16][136] per batch)
    __shared__ __align__(16) char poolB[2][8448];         // nlf (8192B used) then hidh ([16][264])
    int blk = blockIdx.x, t = threadIdx.x;
    int b0 = blk * 2;
    int w = t >> 5, lane = t & 31, g = lane >> 2, tc = lane & 3;

    #pragma unroll
    for (int bb = 0; bb < 2; bb++) {
        const float4* lsrc = (const float4*)(g_lat + (size_t)(b0 + bb) * NLAT * DD);
        for (int i = t; i < 512; i += 256) ((float4*)latv[bb])[i] = lsrc[i];
    }
    __syncthreads();
    // VO GEMM: A-frags straight from global (coalesced uint4), B-frags shared across batches
    {
        const uint32_t* BvP = g_BvoP + (size_t)layer * 65536;
        const float* cvo0 = g_cvo + (layer * 2 + 0) * 128;
        const float* cvo1 = g_cvo + (layer * 2 + 1) * 128;
        const uint32_t* cap0 = g_ctxAP + (size_t)b0 * 16384;
        float acc[2][2][4];
        #pragma unroll
        for (int bb = 0; bb < 2; bb++)
            #pragma unroll
            for (int i = 0; i < 2; i++)
                #pragma unroll
                for (int j = 0; j < 4; j++) acc[bb][i][j] = 0.0f;
        #pragma unroll 4
        for (int ks = 0; ks < 64; ks++) {
            uint2 bf[2];
            #pragma unroll
            for (int nt = 0; nt < 2; nt++)
                bf[nt] = *(const uint2*)(BvP + (size_t)((w * 2 + nt) * 64 + ks) * 64 + lane * 2);
            #pragma unroll
            for (int bb = 0; bb < 2; bb++) {
                uint4 a4 = *(const uint4*)(cap0 + bb * 16384 + ks * 128 + lane * 4);
                uint32_t aA[4] = {a4.x, a4.y, a4.z, a4.w};
                MMA16816(acc[bb][0], aA, bf[0].x, bf[0].y);
                MMA16816(acc[bb][1], aA, bf[1].x, bf[1].y);
            }
        }
        #pragma unroll
        for (int bb = 0; bb < 2; bb++) {
            float* lv = latv[bb];
            #pragma unroll
            for (int nt = 0; nt < 2; nt++) {
                int n0 = w * 16 + nt * 8 + tc * 2;
                float c0v = cvo0[n0] + cvo1[n0];
                float c1v = cvo0[n0 + 1] + cvo1[n0 + 1];
                lv[g * 128 + n0]           += acc[bb][nt][0] + c0v;
                lv[g * 128 + n0 + 1]       += acc[bb][nt][1] + c1v;
                lv[(g + 8) * 128 + n0]     += acc[bb][nt][2] + c0v;
                lv[(g + 8) * 128 + n0 + 1] += acc[bb][nt][3] + c1v;
            }
        }
    }
    __syncthreads();
    layernorm_rows(latv[0], lng, lnb, (float(*)[DD])poolB[0], t, 256);
    layernorm_rows(latv[1], lng, lnb, (float(*)[DD])poolB[1], t, 256);
    __syncthreads();
    for (int i = t; i < NLAT * DD; i += 256) {
        int r = i >> 6, c = (i & 63) * 2;
        int bb = r >> 4, rr = r & 15;
        const float* nlf = (const float*)poolB[bb];
        *(uint32_t*)(nlh[bb] + rr * 136 + c) = f2bf2(nlf[rr * DD + c], nlf[rr * DD + c + 1]);
    }
    __syncthreads();
    // FFN1 (TC): hid = relu(nl @ w1^T + b1) -> hidh overlays nlf in poolB
    {
        const uint32_t* W1P = g_w1P + (size_t)layer * 16384;
        uint32_t aN = s2u(nlh[0] + (lane & 15) * 136 + (lane >> 4) * 8);
        float f1a[2][4][4];
        #pragma unroll
        for (int bb = 0; bb < 2; bb++)
            #pragma unroll
            for (int i = 0; i < 4; i++)
                #pragma unroll
                for (int j = 0; j < 4; j++) f1a[bb][i][j] = 0.0f;
        #pragma unroll
        for (int ks = 0; ks < 8; ks++) {
            uint2 bf[4];
            #pragma unroll
            for (int nt = 0; nt < 4; nt++)
                bf[nt] = *(const uint2*)(W1P + (size_t)((w * 4 + nt) * 8 + ks) * 64 + lane * 2);
            #pragma unroll
            for (int bb = 0; bb < 2; bb++) {
                uint32_t aA[4];
                LDSM4(aA, aN + bb * 4352 + ks * 32);
                #pragma unroll
                for (int nt = 0; nt < 4; nt++) MMA16816(f1a[bb][nt], aA, bf[nt].x, bf[nt].y);
            }
        }
        __syncthreads();  // nlf (poolB) reads in conversion done; now safe to overwrite as hidh
        #pragma unroll
        for (int bb = 0; bb < 2; bb++) {
            __nv_bfloat16* hh = (__nv_bfloat16*)poolB[bb];
            #pragma unroll
            for (int nt = 0; nt < 4; nt++) {
                int n0 = (w * 4 + nt) * 8 + tc * 2;
                float b0v = b1[n0], b1v = b1[n0 + 1];
                *(uint32_t*)(hh + g * 264 + n0) =
                    f2bf2(fmaxf(f1a[bb][nt][0] + b0v, 0.0f), fmaxf(f1a[bb][nt][1] + b1v, 0.0f));
                *(uint32_t*)(hh + (g + 8) * 264 + n0) =
                    f2bf2(fmaxf(f1a[bb][nt][2] + b0v, 0.0f), fmaxf(f1a[bb][nt][3] + b1v, 0.0f));
            }
        }
    }
    __syncthreads();
    // FFN2 (TC) + residual -> g_lat
    {
        const uint32_t* W2P = g_w2P + (size_t)layer * 16384;
        uint32_t aH = s2u((__nv_bfloat16*)poolB[0] + (lane & 15) * 264 + (lane >> 4) * 8);
        float f2a[2][2][4];
        #pragma unroll
        for (int bb = 0; bb < 2; bb++)
            #pragma unroll
            for (int i = 0; i < 2; i++)
                #pragma unroll
                for (int j = 0; j < 4; j++) f2a[bb][i][j] = 0.0f;
        #pragma unroll 4
        for (int ks = 0; ks < 16; ks++) {
            uint2 bf[2];
            #pragma unroll
            for (int nt = 0; nt < 2; nt++)
                bf[nt] = *(const uint2*)(W2P + (size_t)((w * 2 + nt) * 16 + ks) * 64 + lane * 2);
            #pragma unroll
            for (int bb = 0; bb < 2; bb++) {
                uint32_t aA[4];
                LDSM4(aA, aH + bb * 8448 + ks * 32);
                MMA16816(f2a[bb][0], aA, bf[0].x, bf[0].y);
                MMA16816(f2a[bb][1], aA, bf[1].x, bf[1].y);
            }
        }
        #pragma unroll
        for (int bb = 0; bb < 2; bb++) {
            float* latb = g_lat + (size_t)(b0 + bb) * NLAT * DD;
            const float* lv = latv[bb];
            #pragma unroll
            for (int nt = 0; nt < 2; nt++) {
                int n0 = (w * 2 + nt) * 8 + tc * 2;
                float b0v = b2[n0], b1v = b2[n0 + 1];
                latb[g * 128 + n0]           = lv[g * 128 + n0] + f2a[bb][nt][0] + b0v;
                latb[g * 128 + n0 + 1]       = lv[g * 128 + n0 + 1] + f2a[bb][nt][1] + b1v;
                latb[(g + 8) * 128 + n0]     = lv[(g + 8) * 128 + n0] + f2a[bb][nt][2] + b0v;
                latb[(g + 8) * 128 + n0 + 1] = lv[(g + 8) * 128 + n0 + 1] + f2a[bb][nt][3] + b1v;
            }
        }
    }
}

// ---------------- head: grid 128, 4 batches/block ----------------
__global__ void __launch_bounds__(256) head_kernel(
    const float* __restrict__ w1, const float* __restrict__ b1,
    const float* __restrict__ w2, const float* __restrict__ b2,
    float* __restrict__ out) {
    __shared__ float flat_s[4][2048];
    __shared__ float hs[4][128];
    int blk = blockIdx.x, t = threadIdx.x;
    int b0 = blk * 4;
    const float4* src = (const float4*)(g_lat + (size_t)b0 * NLAT * DD);
    for (int i = t; i < 2048; i += 256) ((float4*)flat_s)[i] = src[i];
    __syncthreads();
    int tt = t & 127, bh = t >> 7;
    float acc0 = b1[tt], acc1 = acc0;
    const float4* w1r = (const float4*)(w1 + (size_t)tt * NLAT * DD);
    const float4* f0 = (const float4*)flat_s[bh * 2];
    const float4* f1 = (const float4*)flat_s[bh * 2 + 1];
    #pragma unroll 8
    for (int u4 = 0; u4 < 512; u4++) {
        float4 w4 = w1r[u4];
        float4 a4 = f0[u4];
        float4 c4 = f1[u4];
        acc0 = fmaf(w4.x, a4.x, fmaf(w4.y, a4.y, fmaf(w4.z, a4.z, fmaf(w4.w, a4.w, acc0))));
        acc1 = fmaf(w4.x, c4.x, fmaf(w4.y, c4.y, fmaf(w4.z, c4.z, fmaf(w4.w, c4.w, acc1))));
    }
    hs[bh * 2][tt] = fmaxf(acc0, 0.0f);
    hs[bh * 2 + 1][tt] = fmaxf(acc1, 0.0f);
    __syncthreads();
    int w = t >> 5, lane = t & 31;
    if (w < 4) {
        float s = 0.0f;
        #pragma unroll
        for (int q = 0; q < 4; q++) {
            int idx = q * 32 + lane;
            s += hs[w][idx] * w2[idx];
        }
        #pragma unroll
        for (int o = 16; o; o >>= 1) s += __shfl_xor_sync(0xffffffffu, s, o);
        if (lane == 0) {
            float x = s + b2[0];
            out[b0 + w] = (x > 20.0f) ? x : log1pf(__expf(x));
        }
    }
}

extern "C" void kernel_launch(void* const* d_in, const int* in_sizes, int n_in,
                              void* d_out, int out_size) {
    const float* drug_k   = (const float*)d_in[0];
    const float* drug_v   = (const float*)d_in[1];
    const float* enz_k    = (const float*)d_in[2];
    const float* enz_v    = (const float*)d_in[3];
    const int*   drug_b   = (const int*)d_in[4];
    const int*   enz_b    = (const int*)d_in[5];
    const float* latents  = (const float*)d_in[6];
    const float* wq_d     = (const float*)d_in[7];
    const float* bq_d     = (const float*)d_in[8];
    const float* wq_e     = (const float*)d_in[9];
    const float* bq_e     = (const float*)d_in[10];
    const float* mha_d_w  = (const float*)d_in[11];
    const float* mha_d_b  = (const float*)d_in[12];
    const float* mha_d_ow = (const float*)d_in[13];
    const float* mha_d_ob = (const float*)d_in[14];
    const float* mha_e_w  = (const float*)d_in[15];
    const float* mha_e_b  = (const float*)d_in[16];
    const float* mha_e_ow = (const float*)d_in[17];
    const float* mha_e_ob = (const float*)d_in[18];
    const float* ln1_g    = (const float*)d_in[19];
    const float* ln1_b    = (const float*)d_in[20];
    const float* ln2_g    = (const float*)d_in[21];
    const float* ln2_b    = (const float*)d_in[22];
    const float* ffn_w1   = (const float*)d_in[23];
    const float* ffn_b1   = (const float*)d_in[24];
    const float* ffn_w2   = (const float*)d_in[25];
    const float* ffn_b2   = (const float*)d_in[26];
    const float* head_w1  = (const float*)d_in[27];
    const float* head_b1  = (const float*)d_in[28];
    const float* head_w2  = (const float*)d_in[29];
    const float* head_b2  = (const float*)d_in[30];
    float* out = (float*)d_out;

    static int s_attr_set = 0;
    if (!s_attr_set) {
        cudaFuncSetAttribute(attn_kernel, cudaFuncAttributeMaxDynamicSharedMemorySize, ATT_BYTES);
        s_attr_set = 1;
    }

    mega_setup_kernel<<<SETUP_GRID, 256>>>(
        drug_k, drug_v, enz_k, enz_v, drug_b, enz_b, latents,
        wq_d, bq_d, wq_e, bq_e,
        mha_d_w, mha_d_b, mha_d_ow, mha_d_ob,
        mha_e_w, mha_e_b, mha_e_ow, mha_e_ob,
        ffn_w1, ffn_w2);
    pc_Aq_kernel<<<dim3(32, 4), 256>>>(mha_d_w, mha_e_w);

    for (int l = 0; l < LAYERS; l++) {
        size_t oV = (size_t)l * DD;
        size_t oF1b = (size_t)l * 2 * DD;

        attn_kernel<<<1024, 256, ATT_BYTES>>>(l, ln1_g + oV, ln1_b + oV);
        projffn_kernel<<<BB / 2, 256>>>(l,
            ln2_g + oV, ln2_b + oV,
            ffn_b1 + oF1b, ffn_b2 + oV);
    }

    head_kernel<<<128, 256>>>(head_w1, head_b1, head_w2, head_b2, out);
}

// round 16
// speedup vs baseline: 1.0908x; 1.0908x over previous
#include <cuda_runtime.h>
#include <cuda_bf16.h>
#include <stdint.h>
#include <math.h>

#define BB 512
#define DD 128
#define NLAT 16
#define NH 4
#define HDIM 32
#define ND 25600
#define NE 153600
#define NPAIR 64
#define LAYERS 4

// scratch (static device globals: allowed)
__device__ float g_lat[BB * NLAT * DD];
__device__ __nv_bfloat16 g_ctxh[BB * NLAT * 1024];
__device__ int   g_starts[2][BB + 1];
__device__ __nv_bfloat16 g_dk[ND * DD];
__device__ __nv_bfloat16 g_dv[ND * DD];
__device__ __nv_bfloat16 g_ek[NE * DD];
__device__ __nv_bfloat16 g_ev[NE * DD];
// composed weights, MMA B-fragment packed: [n_tile][kstep][lane][2 words]
__device__ uint32_t g_AqP[LAYERS * 2 * 32768];
__device__ float g_cq[LAYERS * 2 * 512];
__device__ uint32_t g_BvoP[LAYERS * 65536];
__device__ float g_cvo[LAYERS * 2 * 128];
__device__ uint32_t g_w1P[LAYERS * 16384];
__device__ uint32_t g_w2P[LAYERS * 16384];
// precompute scratch
__device__ float g_P[32 * 32 * 128];
__device__ float g_cb[32 * 32];

__device__ __forceinline__ int lb_dev(const int* __restrict__ a, int n, int key) {
    int lo = 0, hi = n;
    while (lo < hi) { int mid = (lo + hi) >> 1; if (a[mid] < key) lo = mid + 1; else hi = mid; }
    return lo;
}

__device__ __forceinline__ uint32_t f2bf2(float x, float y) {
    __nv_bfloat162 h = __floats2bfloat162_rn(x, y);
    return *reinterpret_cast<uint32_t*>(&h);
}

// frag scatter: element (n, k pair j) -> lane = (n&7)*4 + (j&3), word = j>>2
__device__ __forceinline__ void frag_store8(uint32_t* base32, int n_in, const float* acc, float scl) {
    #pragma unroll
    for (int j = 0; j < 8; j++) {
        int lane = n_in * 4 + (j & 3);
        int word = j >> 2;
        base32[lane * 2 + word] = f2bf2(acc[2 * j] * scl, acc[2 * j + 1] * scl);
    }
}

// ---------------- mega setup ----------------
#define PCP0 0
#define PCB0 128
#define CVO0 256
#define FFN0 264
#define OFF0 268
#define INIT0 271
#define CVT0 4367
#define SETUP_GRID 23567

__global__ void __launch_bounds__(256) mega_setup_kernel(
    const float* __restrict__ dk, const float* __restrict__ dv,
    const float* __restrict__ ek, const float* __restrict__ ev,
    const int* __restrict__ db, const int* __restrict__ eb,
    const float* __restrict__ latents,
    const float* __restrict__ wq_d, const float* __restrict__ bq_d,
    const float* __restrict__ wq_e, const float* __restrict__ bq_e,
    const float* __restrict__ mw_d, const float* __restrict__ mb_d,
    const float* __restrict__ ow_d, const float* __restrict__ ob_d,
    const float* __restrict__ mw_e, const float* __restrict__ mb_e,
    const float* __restrict__ ow_e, const float* __restrict__ ob_e,
    const float* __restrict__ w1, const float* __restrict__ w2) {
    __shared__ float sb[8224];
    int bid = blockIdx.x, t = threadIdx.x;

    if (bid >= CVT0) {
        int i = (bid - CVT0) * 256 + t;
        int i4 = i * 4;
        if (i4 < ND * DD) {
            float4 a = *(const float4*)(dk + i4);
            float4 b = *(const float4*)(dv + i4);
            *(uint2*)(g_dk + i4) = make_uint2(f2bf2(a.x, a.y), f2bf2(a.z, a.w));
            *(uint2*)(g_dv + i4) = make_uint2(f2bf2(b.x, b.y), f2bf2(b.z, b.w));
        }
        if (i4 < NE * DD) {
            float4 a = *(const float4*)(ek + i4);
            float4 b = *(const float4*)(ev + i4);
            *(uint2*)(g_ek + i4) = make_uint2(f2bf2(a.x, a.y), f2bf2(a.z, a.w));
            *(uint2*)(g_ev + i4) = make_uint2(f2bf2(b.x, b.y), f2bf2(b.z, b.w));
        }
        return;
    }
    if (bid >= INIT0) {
        int i = (bid - INIT0) * 256 + t;
        if (i < BB * NLAT * DD) g_lat[i] = latents[i & (NLAT * DD - 1)];
        return;
    }
    if (bid >= OFF0) {
        int i = (bid - OFF0) * 256 + t;
        if (i <= BB) { g_starts[0][i] = lb_dev(db, ND, i); g_starts[1][i] = lb_dev(eb, NE, i); }
        return;
    }
    if (bid >= FFN0) {
        int l = bid - FFN0;
        {
            const float* src = w1 + (size_t)l * 2 * DD * DD + (size_t)t * DD;
            int n_t = t >> 3, n_in = t & 7;
            for (int ks = 0; ks < 8; ks++) {
                float v[16];
                #pragma unroll
                for (int q = 0; q < 4; q++) {
                    float4 f = *(const float4*)(src + ks * 16 + q * 4);
                    v[q*4+0] = f.x; v[q*4+1] = f.y; v[q*4+2] = f.z; v[q*4+3] = f.w;
                }
                frag_store8(g_w1P + (size_t)l * 16384 + (size_t)(n_t * 8 + ks) * 64, n_in, v, 1.0f);
            }
        }
        {
            int n = t & 127, half = t >> 7;
            const float* src = w2 + (size_t)l * DD * 2 * DD + (size_t)n * 2 * DD;
            int n_t = n >> 3, n_in = n & 7;
            for (int kk = 0; kk < 8; kk++) {
                int ks = half * 8 + kk;
                float v[16];
                #pragma unroll
                for (int q = 0; q < 4; q++) {
                    float4 f = *(const float4*)(src + ks * 16 + q * 4);
                    v[q*4+0] = f.x; v[q*4+1] = f.y; v[q*4+2] = f.z; v[q*4+3] = f.w;
                }
                frag_store8(g_w2P + (size_t)l * 16384 + (size_t)(n_t * 16 + ks) * 64, n_in, v, 1.0f);
            }
        }
        return;
    }
    if (bid >= CVO0) {
        int r = bid - CVO0;
        int m = r & 1, l = r >> 1;
        const float* ow = (m ? ow_e : ow_d) + (size_t)l * DD * DD;
        const float* ob = (m ? ob_e : ob_d) + l * DD;
        const float* bv = (m ? mb_e : mb_d) + l * 3 * DD + 2 * DD;
        float* bv_s = sb;
        if (t < 128) bv_s[t] = bv[t];
        __syncthreads();
        if (t < 128) {
            float s = ob[t];
            const float4* owr = (const float4*)(ow + (size_t)t * 128);
            #pragma unroll
            for (int u4 = 0; u4 < 32; u4++) {
                float4 o4 = owr[u4];
                s = fmaf(o4.x, bv_s[u4*4+0], fmaf(o4.y, bv_s[u4*4+1],
                    fmaf(o4.z, bv_s[u4*4+2], fmaf(o4.w, bv_s[u4*4+3], s))));
            }
            g_cvo[(l * 2 + m) * 128 + t] = s;
        }
        return;
    }
    if (bid >= PCB0) {
        int r = bid - PCB0;
        int c = r >> 2, ts = r & 3;
        int h = c & 3, m = (c >> 2) & 1, l = c >> 3;
        const float* W  = (m ? mw_e : mw_d) + (size_t)l * 3 * DD * DD;
        const float* ow = (m ? ow_e : ow_d) + (size_t)l * DD * DD;
        float* wv_s = sb;
        float* ow_s = sb + 4096;
        for (int i = t; i < 1024; i += 256)
            ((float4*)wv_s)[i] = ((const float4*)(W + (size_t)(2 * DD + h * 32) * DD))[i];
        for (int i = t; i < 1024; i += 256) {
            int tpl = i >> 5, j = i & 31;
            ow_s[tpl * 32 + j] = ow[(size_t)(ts * 32 + tpl) * 128 + h * 32 + j];
        }
        __syncthreads();
        int tpl = t >> 3, d0 = (t & 7) * 16;
        float acc[16];
        #pragma unroll
        for (int i = 0; i < 16; i++) acc[i] = 0.0f;
        for (int j = 0; j < 32; j++) {
            float o = ow_s[tpl * 32 + j];
            const float4* wr = (const float4*)(wv_s + j * 128 + d0);
            #pragma unroll
            for (int q = 0; q < 4; q++) {
                float4 w4 = wr[q];
                acc[q*4+0] = fmaf(o, w4.x, acc[q*4+0]);
                acc[q*4+1] = fmaf(o, w4.y, acc[q*4+1]);
                acc[q*4+2] = fmaf(o, w4.z, acc[q*4+2]);
                acc[q*4+3] = fmaf(o, w4.w, acc[q*4+3]);
            }
        }
        int n = ts * 32 + tpl;
        int kk0 = m * 512 + h * 128 + d0;
        int n_t = n >> 3, n_in = n & 7, ks = kk0 >> 4;
        frag_store8(g_BvoP + (size_t)l * 65536 + (size_t)(n_t * 64 + ks) * 64, n_in, acc, 1.0f);
        return;
    }
    {
        int r = bid - PCP0;
        int c = r >> 2, ds = r & 3;
        int h = c & 3, m = (c >> 2) & 1, l = c >> 3;
        const float* wq = (m ? wq_e : wq_d) + (size_t)l * DD * DD;
        const float* W  = (m ? mw_e : mw_d) + (size_t)l * 3 * DD * DD;
        float* U_s = sb;
        float* wq_s = sb + 4096;
        for (int i = t; i < 1024; i += 256)
            ((float4*)U_s)[i] = ((const float4*)(W + (size_t)h * 32 * DD))[i];
        for (int i = t; i < 1024; i += 256) {
            int dp = i >> 3, q = i & 7;
            *(float4*)(wq_s + dp * 32 + q * 4) = *(const float4*)(wq + (size_t)dp * 128 + ds * 32 + q * 4);
        }
        __syncthreads();
        int j = t >> 3, dl = (t & 7) * 4;
        float a0 = 0, a1 = 0, a2 = 0, a3 = 0;
        #pragma unroll 8
        for (int dp = 0; dp < 128; dp++) {
            float u = U_s[j * 128 + dp];
            float4 w4 = *(const float4*)(wq_s + dp * 32 + dl);
            a0 = fmaf(u, w4.x, a0); a1 = fmaf(u, w4.y, a1);
            a2 = fmaf(u, w4.z, a2); a3 = fmaf(u, w4.w, a3);
        }
        *(float4*)(g_P + (size_t)c * 4096 + j * 128 + ds * 32 + dl) = make_float4(a0, a1, a2, a3);
        if (ds == 0 && t < 32) {
            const float* bq = (m ? bq_e : bq_d) + l * DD;
            const float* mb = (m ? mb_e : mb_d) + l * 3 * DD;
            float s = 0.0f;
            #pragma unroll 8
            for (int dp = 0; dp < 128; dp++) s += U_s[t * 128 + dp] * bq[dp];
            g_cb[c * 32 + t] = s + mb[h * 32 + t];
        }
    }
}

// pc_Aq depends on g_P -> separate launch
__global__ void __launch_bounds__(256) pc_Aq_kernel(
    const float* __restrict__ mw_d, const float* __restrict__ mw_e) {
    __shared__ float P_s[32 * 128];
    __shared__ float V_s[32 * 32];
    __shared__ float cb_s[32];
    int c = blockIdx.x, ts = blockIdx.y, t = threadIdx.x;
    int h = c & 3, m = (c >> 2) & 1, l = c >> 3;
    const float* W = (m ? mw_e : mw_d) + (size_t)l * 3 * DD * DD;
    const float* wk = W + (size_t)(DD + h * 32) * DD;
    for (int i = t; i < 1024; i += 256)
        ((float4*)P_s)[i] = ((const float4*)(g_P + (size_t)c * 4096))[i];
    for (int i = t; i < 1024; i += 256) {
        int j = i >> 5, tpl = i & 31;
        V_s[j * 32 + tpl] = wk[(size_t)j * 128 + ts * 32 + tpl];
    }
    if (t < 32) cb_s[t] = g_cb[c * 32 + t];
    __syncthreads();
    const float scale = 0.17677669529663688f;
    int tpl = t >> 3, d0 = (t & 7) * 16;
    float acc[16];
    #pragma unroll
    for (int i = 0; i < 16; i++) acc[i] = 0.0f;
    float cq = 0.0f;
    for (int j = 0; j < 32; j++) {
        float v = V_s[j * 32 + tpl];
        const float4* pr = (const float4*)(P_s + j * 128 + d0);
        #pragma unroll
        for (int q = 0; q < 4; q++) {
            float4 p4 = pr[q];
            acc[q*4+0] = fmaf(v, p4.x, acc[q*4+0]);
            acc[q*4+1] = fmaf(v, p4.y, acc[q*4+1]);
            acc[q*4+2] = fmaf(v, p4.z, acc[q*4+2]);
            acc[q*4+3] = fmaf(v, p4.w, acc[q*4+3]);
        }
        cq += v * cb_s[j];
    }
    int n = ts * 32 + tpl;
    int n_t = n >> 3, n_in = n & 7, ks = t & 7;
    frag_store8(g_AqP + (size_t)(l * 2 + m) * 32768 + (size_t)(n_t * 8 + ks) * 64, n_in, acc, scale);
    if ((t & 7) == 0) g_cq[(l * 2 + m) * 512 + n] = cq * scale;
}

// ---------------- common helpers ----------------
__device__ __forceinline__ void layernorm_rows(const float* __restrict__ src,
                                               const float* __restrict__ g,
                                               const float* __restrict__ bta,
                                               float (*dst)[DD], int t, int nthr) {
    int warp = t >> 5, lane = t & 31, nw = nthr >> 5;
    for (int r = warp; r < NLAT; r += nw) {
        float4 v = ((const float4*)(src + r * DD))[lane];
        float s = v.x + v.y + v.z + v.w;
        #pragma unroll
        for (int o = 16; o; o >>= 1) s += __shfl_xor_sync(0xffffffffu, s, o);
        float mean = s * (1.0f / DD);
        float dx = v.x - mean, dy = v.y - mean, dz = v.z - mean, dw = v.w - mean;
        float q = dx * dx + dy * dy + dz * dz + dw * dw;
        #pragma unroll
        for (int o = 16; o; o >>= 1) q += __shfl_xor_sync(0xffffffffu, q, o);
        float rstd = rsqrtf(q * (1.0f / DD) + 1e-5f);
        int c = lane * 4;
        dst[r][c + 0] = dx * rstd * g[c + 0] + bta[c + 0];
        dst[r][c + 1] = dy * rstd * g[c + 1] + bta[c + 1];
        dst[r][c + 2] = dz * rstd * g[c + 2] + bta[c + 2];
        dst[r][c + 3] = dw * rstd * g[c + 3] + bta[c + 3];
    }
}

__device__ __forceinline__ uint32_t s2u(const void* p) {
    return (uint32_t)__cvta_generic_to_shared(p);
}

#define LDSM4(R, addr) asm volatile( \
    "ldmatrix.sync.aligned.m8n8.x4.shared.b16 {%0,%1,%2,%3},[%4];" \
    : "=r"((R)[0]), "=r"((R)[1]), "=r"((R)[2]), "=r"((R)[3]) : "r"(addr))
#define LDSM4T(R, addr) asm volatile( \
    "ldmatrix.sync.aligned.m8n8.x4.trans.shared.b16 {%0,%1,%2,%3},[%4];" \
    : "=r"((R)[0]), "=r"((R)[1]), "=r"((R)[2]), "=r"((R)[3]) : "r"(addr))
#define MMA16816(D, A, B0, B1) asm volatile( \
    "mma.sync.aligned.m16n8k16.row.col.f32.bf16.bf16.f32 " \
    "{%0,%1,%2,%3},{%4,%5,%6,%7},{%8,%9},{%0,%1,%2,%3};" \
    : "+f"((D)[0]), "+f"((D)[1]), "+f"((D)[2]), "+f"((D)[3]) \
    : "r"((A)[0]), "r"((A)[1]), "r"((A)[2]), "r"((A)[3]), "r"(B0), "r"(B1))
#define CP16(dst, src) asm volatile("cp.async.cg.shared.global [%0], [%1], 16;\n" :: "r"(dst), "l"(src))
#define CP_COMMIT() asm volatile("cp.async.commit_group;\n" ::: "memory")
#define CP_WAIT1() asm volatile("cp.async.wait_group 1;\n" ::: "memory")
#define CP_WAIT0() asm volatile("cp.async.wait_group 0;\n" ::: "memory")

// ---------------- fused attention: LN + Q-GEMM prologue + flash attention ----------------
#define KV_ELE (64 * 136)
#define ATT_BYTES (4 * KV_ELE * 2 + 64 * 72 * 2 + 64 * 68 * 4 + 3 * 64 * 4)

__device__ __forceinline__ void issue_chunk(const __nv_bfloat16* __restrict__ Kg,
                                            const __nv_bfloat16* __restrict__ Vg,
                                            __nv_bfloat16* Ksb, __nv_bfloat16* Vsb,
                                            int row0, int nk, int t) {
    #pragma unroll
    for (int i = t; i < 1024; i += 256) {
        int r = i >> 4, seg = (i & 15) * 8;
        if (r < nk) {
            CP16(s2u(Ksb + r * 136 + seg), Kg + (size_t)(row0 + r) * DD + seg);
            CP16(s2u(Vsb + r * 136 + seg), Vg + (size_t)(row0 + r) * DD + seg);
        }
    }
}

// grid 1024: bid<512 -> enzyme first, else drug. 256 threads.
__global__ void __launch_bounds__(256, 2) attn_kernel(int layer,
    const float* __restrict__ lng, const float* __restrict__ lnb) {
    extern __shared__ char smraw[];
    __nv_bfloat16* Ks0 = (__nv_bfloat16*)smraw;
    __nv_bfloat16* Vs0 = Ks0 + 2 * KV_ELE;
    __nv_bfloat16* Ps  = Vs0 + 2 * KV_ELE;
    float* ss  = (float*)(Ps + 64 * 72);
    float* m_s = ss + 64 * 68;
    float* l_s = m_s + 64;
    float* sc_s = l_s + 64;
    float* nlf = (float*)Ps;
    __nv_bfloat16* nlh = Vs0 + KV_ELE;
    __nv_bfloat16* qts = (__nv_bfloat16*)ss;

    int bid = blockIdx.x, t = threadIdx.x;
    int mod = (bid < 512) ? 1 : 0;
    int b = bid & 511;
    const __nv_bfloat16* Kg = mod ? g_ek : g_dk;
    const __nv_bfloat16* Vg = mod ? g_ev : g_dv;
    int w = t >> 5, lane = t & 31;
    int g = lane >> 2, tc = lane & 3;
    int s0 = g_starts[mod][b];
    int cnt = g_starts[mod][b + 1] - s0;

    int pb = (w & 3) * 16;
    int th = w >> 2;

    for (int i = t; i < (4 * KV_ELE * 2) / 16; i += 256)
        ((uint4*)smraw)[i] = make_uint4(0, 0, 0, 0);
    __syncthreads();

    int nchunks = (cnt + 63) >> 6;
    if (nchunks > 0) {
        issue_chunk(Kg, Vg, Ks0, Vs0, s0, min(64, cnt), t);
        CP_COMMIT();
    }

    layernorm_rows(g_lat + (size_t)b * NLAT * DD, lng, lnb, (float(*)[DD])nlf, t, 256);
    __syncthreads();
    for (int i = t; i < NLAT * DD / 2; i += 256) {
        int r = i >> 6, c = (i & 63) * 2;
        *(uint32_t*)(nlh + r * 136 + c) = f2bf2(nlf[r * DD + c], nlf[r * DD + c + 1]);
    }
    __syncthreads();
    {
        const uint32_t* AqP = g_AqP + (size_t)(layer * 2 + mod) * 32768;
        const float* cq = g_cq + (layer * 2 + mod) * 512;
        uint32_t aN = s2u(nlh + (lane & 15) * 136 + (lane >> 4) * 8);
        float acc[8][4];
        #pragma unroll
        for (int i = 0; i < 8; i++)
            #pragma unroll
            for (int j = 0; j < 4; j++) acc[i][j] = 0.0f;
        #pragma unroll
        for (int ks = 0; ks < 8; ks++) {
            uint32_t aA[4];
            LDSM4(aA, aN + ks * 32);
            #pragma unroll
            for (int nt = 0; nt < 8; nt++) {
                int n_t = w * 8 + nt;
                uint2 bb = *(const uint2*)(AqP + (size_t)(n_t * 8 + ks) * 64 + lane * 2);
                MMA16816(acc[nt], aA, bb.x, bb.y);
            }
        }
        #pragma unroll
        for (int nt = 0; nt < 8; nt++) {
            int n0 = w * 64 + nt * 8 + tc * 2;
            int h = n0 >> 7, col = n0 & 127;
            float c0v = cq[n0], c1v = cq[n0 + 1];
            *(uint32_t*)(qts + (g * 4 + h) * 136 + col)       = f2bf2(acc[nt][0] + c0v, acc[nt][1] + c1v);
            *(uint32_t*)(qts + ((g + 8) * 4 + h) * 136 + col) = f2bf2(acc[nt][2] + c0v, acc[nt][3] + c1v);
        }
    }
    __syncthreads();
    uint32_t qa[8][4];
    {
        uint32_t aQ = s2u(qts + (pb + (lane & 15)) * 136 + (lane >> 4) * 8);
        #pragma unroll
        for (int ks = 0; ks < 8; ks++) LDSM4(qa[ks], aQ + ks * 32);
    }
    if (t < 64) { m_s[t] = -1e30f; l_s[t] = 0.0f; }

    float cx[8][4];
    #pragma unroll
    for (int i = 0; i < 8; i++)
        #pragma unroll
        for (int j = 0; j < 4; j++) cx[i][j] = 0.0f;

    uint32_t aK1 = s2u(Ks0 + (th * 32 + ((lane >> 4) << 3) + (lane & 7)) * 136 + ((lane >> 3) & 1) * 8);
    uint32_t aK2 = aK1 + 16 * 136 * 2;
    uint32_t aP  = s2u(Ps + (pb + (lane & 15)) * 72 + (lane >> 4) * 8);
    uint32_t aV  = s2u(Vs0 + (lane & 15) * 136 + th * 64 + (lane >> 4) * 8);

    for (int k = 0; k < nchunks; k++) {
        int cur = k & 1;
        int nk = min(64, cnt - k * 64);
        if (k + 1 < nchunks) {
            int nk2 = min(64, cnt - (k + 1) * 64);
            issue_chunk(Kg, Vg, Ks0 + (cur ^ 1) * KV_ELE, Vs0 + (cur ^ 1) * KV_ELE,
                        s0 + (k + 1) * 64, nk2, t);
            CP_COMMIT();
            CP_WAIT1();
        } else {
            CP_WAIT0();
        }
        __syncthreads();
        {
            uint32_t kbase1 = aK1 + cur * (KV_ELE * 2);
            uint32_t kbase2 = aK2 + cur * (KV_ELE * 2);
            float sa[4][4];
            #pragma unroll
            for (int j = 0; j < 4; j++)
                #pragma unroll
                for (int q = 0; q < 4; q++) sa[j][q] = 0.0f;
            #pragma unroll
            for (int ks = 0; ks < 8; ks++) {
                uint32_t kb1[4], kb2[4];
                LDSM4(kb1, kbase1 + ks * 32);
                LDSM4(kb2, kbase2 + ks * 32);
                MMA16816(sa[0], qa[ks], kb1[0], kb1[1]);
                MMA16816(sa[1], qa[ks], kb1[2], kb1[3]);
                MMA16816(sa[2], qa[ks], kb2[0], kb2[1]);
                MMA16816(sa[3], qa[ks], kb2[2], kb2[3]);
            }
            int r0 = pb + g, r1 = pb + g + 8;
            #pragma unroll
            for (int j = 0; j < 4; j++) {
                int c0 = th * 32 + j * 8 + tc * 2;
                *(float2*)&ss[r0 * 68 + c0] = make_float2(sa[j][0], sa[j][1]);
                *(float2*)&ss[r1 * 68 + c0] = make_float2(sa[j][2], sa[j][3]);
            }
        }
        __syncthreads();
        {
            int p = t >> 2, sub = t & 3;
            int k0 = sub * 16;
            float mo = m_s[p];
            float cm = -1e30f;
            #pragma unroll 4
            for (int kk = k0; kk < k0 + 16; kk++) {
                float v = (kk < nk) ? ss[p * 68 + kk] : -1e30f;
                cm = fmaxf(cm, v);
            }
            cm = fmaxf(cm, __shfl_xor_sync(0xffffffffu, cm, 1));
            cm = fmaxf(cm, __shfl_xor_sync(0xffffffffu, cm, 2));
            cm = fmaxf(cm, mo);
            float sum = 0.0f;
            #pragma unroll 4
            for (int kk = k0; kk < k0 + 16; kk++) {
                float e = (kk < nk) ? __expf(ss[p * 68 + kk] - cm) : 0.0f;
                Ps[p * 72 + kk] = __float2bfloat16(e);
                sum += e;
            }
            sum += __shfl_xor_sync(0xffffffffu, sum, 1);
            sum += __shfl_xor_sync(0xffffffffu, sum, 2);
            if (sub == 0) {
                float scl = __expf(mo - cm);
                l_s[p] = l_s[p] * scl + sum;
                m_s[p] = cm;
                sc_s[p] = scl;
            }
        }
        __syncthreads();
        {
            uint32_t vbase = aV + cur * (KV_ELE * 2);
            float sc0 = sc_s[pb + g], sc1 = sc_s[pb + g + 8];
            #pragma unroll
            for (int nt = 0; nt < 8; nt++) {
                cx[nt][0] *= sc0; cx[nt][1] *= sc0;
                cx[nt][2] *= sc1; cx[nt][3] *= sc1;
            }
            #pragma unroll
            for (int ks = 0; ks < 4; ks++) {
                uint32_t pa[4];
                LDSM4(pa, aP + ks * 32);
                #pragma unroll
                for (int ntp = 0; ntp < 4; ntp++) {
                    uint32_t vb[4];
                    LDSM4T(vb, vbase + ks * 4352 + ntp * 32);
                    MMA16816(cx[ntp * 2 + 0], pa, vb[0], vb[1]);
                    MMA16816(cx[ntp * 2 + 1], pa, vb[2], vb[3]);
                }
            }
        }
        __syncthreads();
    }
    int r0 = pb + g, r1 = pb + g + 8;
    float l0 = l_s[r0], l1 = l_s[r1];
    float i0 = (l0 > 0.0f) ? 1.0f / l0 : 0.0f;
    float i1 = (l1 > 0.0f) ? 1.0f / l1 : 0.0f;
    __nv_bfloat16* cbp = g_ctxh + (size_t)b * 16384;
    int base0 = (r0 >> 2) * 1024 + mod * 512 + (r0 & 3) * 128;
    int base1 = (r1 >> 2) * 1024 + mod * 512 + (r1 & 3) * 128;
    #pragma unroll
    for (int nt = 0; nt < 8; nt++) {
        int d0 = th * 64 + nt * 8 + tc * 2;
        *(uint32_t*)(cbp + base0 + d0) = f2bf2(cx[nt][0] * i0, cx[nt][1] * i0);
        *(uint32_t*)(cbp + base1 + d0) = f2bf2(cx[nt][2] * i1, cx[nt][3] * i1);
    }
}

// ---------------- fused: VO GEMM + residual + LN2 + FFN (all TC), 1 batch/block ----------------
// dsm: phase A: ctxs [16][1032] bf16 (33024B). After: nlf f32 @0 (8192B),
// nlh bf16 @8192 ([16][136]=4352B), hidh bf16 @16384 ([16][264]=8448B). latv @33024 (8192B).
#define PF_BYTES (33024 + 8192)

__global__ void __launch_bounds__(256) projffn_kernel(int layer,
    const float* __restrict__ lng, const float* __restrict__ lnb,
    const float* __restrict__ b1, const float* __restrict__ b2) {
    extern __shared__ char dsm[];
    __nv_bfloat16* ctxs = (__nv_bfloat16*)dsm;
    float* nlf = (float*)dsm;
    __nv_bfloat16* nlh = (__nv_bfloat16*)(dsm + 8192);
    __nv_bfloat16* hidh = (__nv_bfloat16*)(dsm + 16384);
    float* latv = (float*)(dsm + 33024);
    int b = blockIdx.x, t = threadIdx.x;
    int w = t >> 5, lane = t & 31, g = lane >> 2, tc = lane & 3;

    {
        const uint4* src = (const uint4*)(g_ctxh + (size_t)b * 16384);
        for (int i = t; i < 2048; i += 256) {
            int r = i >> 7, c8 = i & 127;
            *(uint4*)(ctxs + r * 1032 + c8 * 8) = src[i];
        }
        const float4* lsrc = (const float4*)(g_lat + (size_t)b * NLAT * DD);
        for (int i = t; i < 512; i += 256) ((float4*)latv)[i] = lsrc[i];
    }
    __syncthreads();
    // phase A: VO GEMM (packed Bvo) -> latv
    {
        const uint32_t* BvP = g_BvoP + (size_t)layer * 65536;
        const float* cvo0 = g_cvo + (layer * 2 + 0) * 128;
        const float* cvo1 = g_cvo + (layer * 2 + 1) * 128;
        uint32_t aC = s2u(ctxs + (lane & 15) * 1032 + (lane >> 4) * 8);
        float acc[2][4];
        #pragma unroll
        for (int i = 0; i < 2; i++)
            #pragma unroll
            for (int j = 0; j < 4; j++) acc[i][j] = 0.0f;
        #pragma unroll 4
        for (int ks = 0; ks < 64; ks++) {
            uint32_t aA[4];
            LDSM4(aA, aC + ks * 32);
            #pragma unroll
            for (int nt = 0; nt < 2; nt++) {
                int n_t = w * 2 + nt;
                uint2 bb = *(const uint2*)(BvP + (size_t)(n_t * 64 + ks) * 64 + lane * 2);
                MMA16816(acc[nt], aA, bb.x, bb.y);
            }
        }
        __syncthreads();   // all ctxs reads done before nlf overlay
        #pragma unroll
        for (int nt = 0; nt < 2; nt++) {
            int n0 = w * 16 + nt * 8 + tc * 2;
            float c0v = cvo0[n0] + cvo1[n0];
            float c1v = cvo0[n0 + 1] + cvo1[n0 + 1];
            latv[g * 128 + n0]           += acc[nt][0] + c0v;
            latv[g * 128 + n0 + 1]       += acc[nt][1] + c1v;
            latv[(g + 8) * 128 + n0]     += acc[nt][2] + c0v;
            latv[(g + 8) * 128 + n0 + 1] += acc[nt][3] + c1v;
        }
    }
    __syncthreads();
    layernorm_rows(latv, lng, lnb, (float(*)[DD])nlf, t, 256);
    __syncthreads();
    for (int i = t; i < NLAT * DD / 2; i += 256) {
        int r = i >> 6, c = (i & 63) * 2;
        *(uint32_t*)(nlh + r * 136 + c) = f2bf2(nlf[r * DD + c], nlf[r * DD + c + 1]);
    }
    __syncthreads();
    // FFN1 (TC): hid = relu(nl @ w1^T + b1), bf16 -> hidh [16][264]
    {
        const uint32_t* W1P = g_w1P + (size_t)layer * 16384;
        uint32_t aN = s2u(nlh + (lane & 15) * 136 + (lane >> 4) * 8);
        float f1a[4][4];
        #pragma unroll
        for (int i = 0; i < 4; i++)
            #pragma unroll
            for (int j = 0; j < 4; j++) f1a[i][j] = 0.0f;
        #pragma unroll
        for (int ks = 0; ks < 8; ks++) {
            uint32_t aA[4];
            LDSM4(aA, aN + ks * 32);
            #pragma unroll
            for (int nt = 0; nt < 4; nt++) {
                int n_t = w * 4 + nt;
                uint2 bb = *(const uint2*)(W1P + (size_t)(n_t * 8 + ks) * 64 + lane * 2);
                MMA16816(f1a[nt], aA, bb.x, bb.y);
            }
        }
        #pragma unroll
        for (int nt = 0; nt < 4; nt++) {
            int n0 = (w * 4 + nt) * 8 + tc * 2;
            float b0v = b1[n0], b1v = b1[n0 + 1];
            *(uint32_t*)(hidh + g * 264 + n0) =
                f2bf2(fmaxf(f1a[nt][0] + b0v, 0.0f), fmaxf(f1a[nt][1] + b1v, 0.0f));
            *(uint32_t*)(hidh + (g + 8) * 264 + n0) =
                f2bf2(fmaxf(f1a[nt][2] + b0v, 0.0f), fmaxf(f1a[nt][3] + b1v, 0.0f));
        }
    }
    __syncthreads();
    // FFN2 (TC) + residual -> g_lat
    {
        const uint32_t* W2P = g_w2P + (size_t)layer * 16384;
        uint32_t aH = s2u(hidh + (lane & 15) * 264 + (lane >> 4) * 8);
        float f2a[2][4];
        #pragma unroll
        for (int i = 0; i < 2; i++)
            #pragma unroll
            for (int j = 0; j < 4; j++) f2a[i][j] = 0.0f;
        #pragma unroll 4
        for (int ks = 0; ks < 16; ks++) {
            uint32_t aA[4];
            LDSM4(aA, aH + ks * 32);
            #pragma unroll
            for (int nt = 0; nt < 2; nt++) {
                int n_t = w * 2 + nt;
                uint2 bb = *(const uint2*)(W2P + (size_t)(n_t * 16 + ks) * 64 + lane * 2);
                MMA16816(f2a[nt], aA, bb.x, bb.y);
            }
        }
        float* latb = g_lat + (size_t)b * NLAT * DD;
        #pragma unroll
        for (int nt = 0; nt < 2; nt++) {
            int n0 = (w * 2 + nt) * 8 + tc * 2;
            float b0v = b2[n0], b1v = b2[n0 + 1];
            latb[g * 128 + n0]           = latv[g * 128 + n0] + f2a[nt][0] + b0v;
            latb[g * 128 + n0 + 1]       = latv[g * 128 + n0 + 1] + f2a[nt][1] + b1v;
            latb[(g + 8) * 128 + n0]     = latv[(g + 8) * 128 + n0] + f2a[nt][2] + b0v;
            latb[(g + 8) * 128 + n0 + 1] = latv[(g + 8) * 128 + n0 + 1] + f2a[nt][3] + b1v;
        }
    }
}

// ---------------- head: grid 128, 4 batches/block ----------------
__global__ void __launch_bounds__(256) head_kernel(
    const float* __restrict__ w1, const float* __restrict__ b1,
    const float* __restrict__ w2, const float* __restrict__ b2,
    float* __restrict__ out) {
    __shared__ float flat_s[4][2048];
    __shared__ float hs[4][128];
    int blk = blockIdx.x, t = threadIdx.x;
    int b0 = blk * 4;
    const float4* src = (const float4*)(g_lat + (size_t)b0 * NLAT * DD);
    for (int i = t; i < 2048; i += 256) ((float4*)flat_s)[i] = src[i];
    __syncthreads();
    int tt = t & 127, bh = t >> 7;
    float acc0 = b1[tt], acc1 = acc0;
    const float4* w1r = (const float4*)(w1 + (size_t)tt * NLAT * DD);
    const float4* f0 = (const float4*)flat_s[bh * 2];
    const float4* f1 = (const float4*)flat_s[bh * 2 + 1];
    #pragma unroll 8
    for (int u4 = 0; u4 < 512; u4++) {
        float4 w4 = w1r[u4];
        float4 a4 = f0[u4];
        float4 c4 = f1[u4];
        acc0 = fmaf(w4.x, a4.x, fmaf(w4.y, a4.y, fmaf(w4.z, a4.z, fmaf(w4.w, a4.w, acc0))));
        acc1 = fmaf(w4.x, c4.x, fmaf(w4.y, c4.y, fmaf(w4.z, c4.z, fmaf(w4.w, c4.w, acc1))));
    }
    hs[bh * 2][tt] = fmaxf(acc0, 0.0f);
    hs[bh * 2 + 1][tt] = fmaxf(acc1, 0.0f);
    __syncthreads();
    int w = t >> 5, lane = t & 31;
    if (w < 4) {
        float s = 0.0f;
        #pragma unroll
        for (int q = 0; q < 4; q++) {
            int idx = q * 32 + lane;
            s += hs[w][idx] * w2[idx];
        }
        #pragma unroll
        for (int o = 16; o; o >>= 1) s += __shfl_xor_sync(0xffffffffu, s, o);
        if (lane == 0) {
            float x = s + b2[0];
            out[b0 + w] = (x > 20.0f) ? x : log1pf(__expf(x));
        }
    }
}

extern "C" void kernel_launch(void* const* d_in, const int* in_sizes, int n_in,
                              void* d_out, int out_size) {
    const float* drug_k   = (const float*)d_in[0];
    const float* drug_v   = (const float*)d_in[1];
    const float* enz_k    = (const float*)d_in[2];
    const float* enz_v    = (const float*)d_in[3];
    const int*   drug_b   = (const int*)d_in[4];
    const int*   enz_b    = (const int*)d_in[5];
    const float* latents  = (const float*)d_in[6];
    const float* wq_d     = (const float*)d_in[7];
    const float* bq_d     = (const float*)d_in[8];
    const float* wq_e     = (const float*)d_in[9];
    const float* bq_e     = (const float*)d_in[10];
    const float* mha_d_w  = (const float*)d_in[11];
    const float* mha_d_b  = (const float*)d_in[12];
    const float* mha_d_ow = (const float*)d_in[13];
    const float* mha_d_ob = (const float*)d_in[14];
    const float* mha_e_w  = (const float*)d_in[15];
    const float* mha_e_b  = (const float*)d_in[16];
    const float* mha_e_ow = (const float*)d_in[17];
    const float* mha_e_ob = (const float*)d_in[18];
    const float* ln1_g    = (const float*)d_in[19];
    const float* ln1_b    = (const float*)d_in[20];
    const float* ln2_g    = (const float*)d_in[21];
    const float* ln2_b    = (const float*)d_in[22];
    const float* ffn_w1   = (const float*)d_in[23];
    const float* ffn_b1   = (const float*)d_in[24];
    const float* ffn_w2   = (const float*)d_in[25];
    const float* ffn_b2   = (const float*)d_in[26];
    const float* head_w1  = (const float*)d_in[27];
    const float* head_b1  = (const float*)d_in[28];
    const float* head_w2  = (const float*)d_in[29];
    const float* head_b2  = (const float*)d_in[30];
    float* out = (float*)d_out;

    static int s_attr_set = 0;
    if (!s_attr_set) {
        cudaFuncSetAttribute(attn_kernel, cudaFuncAttributeMaxDynamicSharedMemorySize, ATT_BYTES);
        cudaFuncSetAttribute(projffn_kernel, cudaFuncAttributeMaxDynamicSharedMemorySize, PF_BYTES);
        s_attr_set = 1;
    }

    mega_setup_kernel<<<SETUP_GRID, 256>>>(
        drug_k, drug_v, enz_k, enz_v, drug_b, enz_b, latents,
        wq_d, bq_d, wq_e, bq_e,
        mha_d_w, mha_d_b, mha_d_ow, mha_d_ob,
        mha_e_w, mha_e_b, mha_e_ow, mha_e_ob,
        ffn_w1, ffn_w2);
    pc_Aq_kernel<<<dim3(32, 4), 256>>>(mha_d_w, mha_e_w);

    for (int l = 0; l < LAYERS; l++) {
        size_t oV = (size_t)l * DD;
        size_t oF1b = (size_t)l * 2 * DD;

        attn_kernel<<<1024, 256, ATT_BYTES>>>(l, ln1_g + oV, ln1_b + oV);
        projffn_kernel<<<BB, 256, PF_BYTES>>>(l,
            ln2_g + oV, ln2_b + oV,
            ffn_b1 + oF1b, ffn_b2 + oV);
    }

    head_kernel<<<128, 256>>>(head_w1, head_b1, head_w2, head_b2, out);
}